// round 8
// baseline (speedup 1.0000x reference)
#include <cuda_runtime.h>
#include <cuda_bf16.h>

// CBOW negative-sampling loss — single fused kernel, 2 rows per warp.
// Inputs (metadata order):
//   d_in[0] i_emb        float32  (VOCAB+1, 50)
//   d_in[1] o_emb        float32  (VOCAB+1, 50)
//   d_in[2] target_wids  int32    (B,)
//   d_in[3] context_wids int32    (B, 10)
//   d_in[4] neg_wids     int32    (B, 10)
// Output: scalar float32 = -( sum log_sigmoid(pos) + sum log_sigmoid(-neg) )
//
// Each warp owns rows r0=2w and r1=2w+1: 42 independent row gathers in
// flight (lanes 0..24 load one float2 each; rows are 200 B, 8B-aligned).
// Indices for both rows load as vectorized int2 (21 loads for 42 indices).
// The 22 scores reduce as 11 pairs (row0-k with row1-k): one xor-16
// exchange + 4 butterfly steps per pair. Single fused launch via
// last-block-reduces ticket.

#define DIM2 25    // 50 floats = 25 float2
#define CTX  10
#define NNEG 10
#define MAX_BLOCKS 8192

__device__ float        g_partials[MAX_BLOCKS];
__device__ unsigned int g_count = 0;   // module-load init; reset by last block

__device__ __forceinline__ float log_sigmoid(float x) {
    return fminf(x, 0.0f) - log1pf(__expf(-fabsf(x)));
}

// Reduce two independent per-lane partials A,B across the warp in 5 shfls.
// Post: lanes 0-15 hold full sum of A; lanes 16-31 hold full sum of B.
__device__ __forceinline__ float pair_reduce(float A, float B, int lane) {
    float x = (lane & 16) ? A : B;
    float y = __shfl_xor_sync(0xFFFFFFFFu, x, 16);
    float v = ((lane & 16) ? B : A) + y;
    v += __shfl_xor_sync(0xFFFFFFFFu, v, 8);
    v += __shfl_xor_sync(0xFFFFFFFFu, v, 4);
    v += __shfl_xor_sync(0xFFFFFFFFu, v, 2);
    v += __shfl_xor_sync(0xFFFFFFFFu, v, 1);
    return v;
}

__global__ void __launch_bounds__(256) cbow_fused2_kernel(
    const float* __restrict__ i_emb,
    const float* __restrict__ o_emb,
    const int*   __restrict__ target_wids,
    const int*   __restrict__ context_wids,
    const int*   __restrict__ neg_wids,
    float*       __restrict__ out,
    int B)
{
    const int warp_global = (blockIdx.x * blockDim.x + threadIdx.x) >> 5;
    const int lane        = threadIdx.x & 31;
    const int warp_local  = threadIdx.x >> 5;

    __shared__ float  s_partial[8];
    __shared__ int    s_is_last;
    __shared__ double s_d[8];

    const int r0 = warp_global * 2;
    const int r1 = r0 + 1;

    float loss = 0.0f;   // meaningful only on lanes 0 and 16 until combined

    const float2* __restrict__ i2 = (const float2*)i_emb;
    const float2* __restrict__ o2 = (const float2*)o_emb;
    const float   inv_ctx = 1.0f / CTX;

    if (r1 < B) {
        // ---- vectorized index loads: both rows are contiguous ----
        const int2* __restrict__ cw2 = (const int2*)(context_wids + (long)r0 * CTX);
        const int2* __restrict__ nw2 = (const int2*)(neg_wids     + (long)r0 * NNEG);
        const int2  tg = __ldg((const int2*)(target_wids + r0));

        int ci[2 * CTX], ni[2 * NNEG];
        #pragma unroll
        for (int k = 0; k < CTX; k++) {          // 10 int2 = 20 ctx indices
            int2 v = __ldg(&cw2[k]);
            ci[2 * k] = v.x;  ci[2 * k + 1] = v.y;
        }
        #pragma unroll
        for (int k = 0; k < NNEG; k++) {         // 10 int2 = 20 neg indices
            int2 v = __ldg(&nw2[k]);
            ni[2 * k] = v.x;  ni[2 * k + 1] = v.y;
        }

        float ax0 = 0.0f, ay0 = 0.0f, ax1 = 0.0f, ay1 = 0.0f;
        float p0[NNEG + 1], p1[NNEG + 1];
        #pragma unroll
        for (int k = 0; k <= NNEG; k++) { p0[k] = 0.0f; p1[k] = 0.0f; }

        if (lane < DIM2) {
            // ---- context sums, both rows interleaved (20 gathers in flight)
            #pragma unroll
            for (int c = 0; c < CTX; c++) {
                const float2 e0 = __ldg(&i2[(long)ci[c]       * DIM2 + lane]);
                const float2 e1 = __ldg(&i2[(long)ci[CTX + c] * DIM2 + lane]);
                ax0 += e0.x;  ay0 += e0.y;
                ax1 += e1.x;  ay1 += e1.y;
            }

            // ---- 22 score partials (22 gathers in flight) ----
            {
                const float2 e0 = __ldg(&o2[(long)tg.x * DIM2 + lane]);
                const float2 e1 = __ldg(&o2[(long)tg.y * DIM2 + lane]);
                p0[0] = e0.x * ax0 + e0.y * ay0;
                p1[0] = e1.x * ax1 + e1.y * ay1;
            }
            #pragma unroll
            for (int n = 0; n < NNEG; n++) {
                const float2 e0 = __ldg(&o2[(long)ni[n]        * DIM2 + lane]);
                const float2 e1 = __ldg(&o2[(long)ni[NNEG + n] * DIM2 + lane]);
                p0[n + 1] = e0.x * ax0 + e0.y * ay0;
                p1[n + 1] = e1.x * ax1 + e1.y * ay1;
            }
        }

        // ---- reductions: pair score k of row0 with score k of row1 ----
        // k = 0: positive score for both rows
        {
            float v = pair_reduce(p0[0], p1[0], lane);
            if ((lane & 15) == 0)
                loss += log_sigmoid(v * inv_ctx);
        }
        #pragma unroll
        for (int k = 1; k <= NNEG; k++) {
            float v = pair_reduce(p0[k], p1[k], lane);
            if ((lane & 15) == 0)
                loss += log_sigmoid(-v * inv_ctx);
        }
    }
    else if (r0 < B) {
        // ---- tail: single row (only if B is odd; unused for B=16384) ----
        const int* __restrict__ cw = context_wids + (long)r0 * CTX;
        const int* __restrict__ nw = neg_wids     + (long)r0 * NNEG;

        float ax = 0.0f, ay = 0.0f;
        float p[NNEG + 1];
        #pragma unroll
        for (int k = 0; k <= NNEG; k++) p[k] = 0.0f;

        if (lane < DIM2) {
            #pragma unroll
            for (int c = 0; c < CTX; c++) {
                const float2 e = __ldg(&i2[(long)__ldg(&cw[c]) * DIM2 + lane]);
                ax += e.x;  ay += e.y;
            }
            {
                const float2 e = __ldg(&o2[(long)__ldg(&target_wids[r0]) * DIM2 + lane]);
                p[0] = e.x * ax + e.y * ay;
            }
            #pragma unroll
            for (int n = 0; n < NNEG; n++) {
                const float2 e = __ldg(&o2[(long)__ldg(&nw[n]) * DIM2 + lane]);
                p[n + 1] = e.x * ax + e.y * ay;
            }
        }
        #pragma unroll
        for (int k = 0; k <= NNEG; k++) {
            float v = p[k];
            #pragma unroll
            for (int o = 16; o > 0; o >>= 1)
                v += __shfl_xor_sync(0xFFFFFFFFu, v, o);
            if (lane == 0)
                loss += log_sigmoid((k == 0 ? v : -v) * inv_ctx);
        }
    }

    // combine lanes 0 and 16
    loss += __shfl_xor_sync(0xFFFFFFFFu, loss, 16);
    if (lane == 0) s_partial[warp_local] = loss;
    __syncthreads();

    // block partial + last-block ticket
    if (threadIdx.x == 0) {
        float blk = 0.0f;
        #pragma unroll
        for (int i = 0; i < 8; i++) blk += s_partial[i];
        g_partials[blockIdx.x] = blk;
        __threadfence();
        unsigned int old = atomicAdd(&g_count, 1u);
        s_is_last = (old == gridDim.x - 1);
    }
    __syncthreads();

    if (s_is_last) {
        const int nb = gridDim.x;
        volatile float* vp = g_partials;   // writers fenced before the ticket
        double acc = 0.0;
        for (int i = threadIdx.x; i < nb; i += 256)
            acc += (double)vp[i];
        #pragma unroll
        for (int o = 16; o > 0; o >>= 1)
            acc += __shfl_xor_sync(0xFFFFFFFFu, acc, o);
        if ((threadIdx.x & 31) == 0) s_d[threadIdx.x >> 5] = acc;
        __syncthreads();
        if (threadIdx.x == 0) {
            double t = 0.0;
            #pragma unroll
            for (int i = 0; i < 8; i++) t += s_d[i];
            out[0] = (float)(-t);
            g_count = 0;   // reset for next graph replay
        }
    }
}

extern "C" void kernel_launch(void* const* d_in, const int* in_sizes, int n_in,
                              void* d_out, int out_size)
{
    const float* i_emb        = (const float*)d_in[0];
    const float* o_emb        = (const float*)d_in[1];
    const int*   target_wids  = (const int*)d_in[2];
    const int*   context_wids = (const int*)d_in[3];
    const int*   neg_wids     = (const int*)d_in[4];
    float*       out          = (float*)d_out;

    const int B = in_sizes[2];
    const int rows_per_block = 8 * 2;    // 8 warps x 2 rows
    int blocks = (B + rows_per_block - 1) / rows_per_block;
    if (blocks > MAX_BLOCKS) blocks = MAX_BLOCKS;   // B=16384 -> 1024 blocks

    cbow_fused2_kernel<<<blocks, 256>>>(i_emb, o_emb, target_wids,
                                        context_wids, neg_wids, out, B);
}

// round 9
// speedup vs baseline: 1.0226x; 1.0226x over previous
#include <cuda_runtime.h>
#include <cuda_bf16.h>

// CBOW negative-sampling loss — single fused kernel.
// Inputs (metadata order):
//   d_in[0] i_emb        float32  (VOCAB+1, 50)
//   d_in[1] o_emb        float32  (VOCAB+1, 50)
//   d_in[2] target_wids  int32    (B,)
//   d_in[3] context_wids int32    (B, 10)
//   d_in[4] neg_wids     int32    (B, 10)
// Output: scalar float32 = -( sum log_sigmoid(pos) + sum log_sigmoid(-neg) )
//
// One warp per row, 128-thread blocks (finer wave granularity, higher
// occupancy at 38 regs). Rows are 50 floats = 200 B, 8B-aligned: lanes
// 0..24 each load one float2 -> one warp-load per gather. All index math
// is 32-bit (max offset 5M << 2^31). Scores reduce pairwise (5 shfls per
// 2 scores). log_sigmoid uses MUFU __logf/__expf (z in (0,1] so 1+z is
// well-conditioned). Single launch via last-block-reduces ticket.

#define DIM2 25    // 50 floats = 25 float2
#define CTX  10
#define NNEG 10
#define MAX_BLOCKS 8192

__device__ float        g_partials[MAX_BLOCKS];
__device__ unsigned int g_count = 0;   // module-load init; reset by last block

__device__ __forceinline__ float log_sigmoid(float x) {
    // min(x,0) - log(1 + exp(-|x|)); arg of log in (1,2] -> __logf is safe
    return fminf(x, 0.0f) - __logf(1.0f + __expf(-fabsf(x)));
}

// Reduce two independent per-lane partials A,B across the warp in 5 shfls.
// Post: lane 0 holds full sum of A; lane 16 holds full sum of B.
__device__ __forceinline__ float pair_reduce(float A, float B, int lane) {
    float x = (lane & 16) ? A : B;
    float y = __shfl_xor_sync(0xFFFFFFFFu, x, 16);
    float v = ((lane & 16) ? B : A) + y;
    v += __shfl_xor_sync(0xFFFFFFFFu, v, 8);
    v += __shfl_xor_sync(0xFFFFFFFFu, v, 4);
    v += __shfl_xor_sync(0xFFFFFFFFu, v, 2);
    v += __shfl_xor_sync(0xFFFFFFFFu, v, 1);
    return v;
}

__global__ void __launch_bounds__(128) cbow_fused_kernel(
    const float* __restrict__ i_emb,
    const float* __restrict__ o_emb,
    const int*   __restrict__ target_wids,
    const int*   __restrict__ context_wids,
    const int*   __restrict__ neg_wids,
    float*       __restrict__ out,
    int B)
{
    const int warp_global = (blockIdx.x * blockDim.x + threadIdx.x) >> 5;
    const int lane        = threadIdx.x & 31;
    const int warp_local  = threadIdx.x >> 5;

    __shared__ float  s_partial[4];
    __shared__ int    s_is_last;
    __shared__ double s_d[4];

    float loss = 0.0f;   // meaningful only on lanes 0 and 16 until combined

    if (warp_global < B) {
        const float2* __restrict__ i2 = (const float2*)i_emb;
        const float2* __restrict__ o2 = (const float2*)o_emb;
        const int*    __restrict__ cw = context_wids + warp_global * CTX;
        const int*    __restrict__ nw = neg_wids     + warp_global * NNEG;

        // ---- 32-bit row offsets (max 200001*25 = 5000025 < 2^31) ----
        int cb[CTX], nb[NNEG], tb;
        #pragma unroll
        for (int c = 0; c < CTX; c++)  cb[c] = __ldg(&cw[c]) * DIM2;
        tb = __ldg(&target_wids[warp_global]) * DIM2;
        #pragma unroll
        for (int n = 0; n < NNEG; n++) nb[n] = __ldg(&nw[n]) * DIM2;

        float ax = 0.0f, ay = 0.0f;
        float p[NNEG + 1];
        #pragma unroll
        for (int k = 0; k <= NNEG; k++) p[k] = 0.0f;

        if (lane < DIM2) {
            // ---- sum of context embeddings (fold 1/CTX into score) ----
            #pragma unroll
            for (int c = 0; c < CTX; c++) {
                const float2 e = __ldg(&i2[cb[c] + lane]);
                ax += e.x;  ay += e.y;
            }
            // ---- 11 per-lane score partials ----
            {
                const float2 e = __ldg(&o2[tb + lane]);
                p[0] = e.x * ax + e.y * ay;
            }
            #pragma unroll
            for (int n = 0; n < NNEG; n++) {
                const float2 e = __ldg(&o2[nb[n] + lane]);
                p[n + 1] = e.x * ax + e.y * ay;
            }
        }

        const float inv_ctx = 1.0f / CTX;

        // pair 0: (pos, neg0) — mixed signs
        {
            float v = pair_reduce(p[0], p[1], lane);
            if ((lane & 15) == 0) {
                float sc = v * inv_ctx;
                loss += log_sigmoid((lane & 16) ? -sc : sc);
            }
        }
        // pairs (neg1,neg2) (neg3,neg4) (neg5,neg6) (neg7,neg8)
        #pragma unroll
        for (int k = 2; k <= 8; k += 2) {
            float v = pair_reduce(p[k], p[k + 1], lane);
            if ((lane & 15) == 0)
                loss += log_sigmoid(-v * inv_ctx);
        }
        // leftover neg9: plain butterfly, accumulate at lane 0 only
        {
            float v = p[10];
            #pragma unroll
            for (int o = 16; o > 0; o >>= 1)
                v += __shfl_xor_sync(0xFFFFFFFFu, v, o);
            if (lane == 0)
                loss += log_sigmoid(-v * inv_ctx);
        }
    }

    // combine lanes 0 and 16
    loss += __shfl_xor_sync(0xFFFFFFFFu, loss, 16);
    if (lane == 0) s_partial[warp_local] = loss;
    __syncthreads();

    // block partial + last-block ticket
    if (threadIdx.x == 0) {
        float blk = s_partial[0] + s_partial[1] + s_partial[2] + s_partial[3];
        g_partials[blockIdx.x] = blk;
        __threadfence();
        unsigned int old = atomicAdd(&g_count, 1u);
        s_is_last = (old == gridDim.x - 1);
    }
    __syncthreads();

    if (s_is_last) {
        const int nb2 = gridDim.x;
        volatile float* vp = g_partials;   // writers fenced before the ticket
        double acc = 0.0;
        for (int i = threadIdx.x; i < nb2; i += 128)
            acc += (double)vp[i];
        #pragma unroll
        for (int o = 16; o > 0; o >>= 1)
            acc += __shfl_xor_sync(0xFFFFFFFFu, acc, o);
        if ((threadIdx.x & 31) == 0) s_d[threadIdx.x >> 5] = acc;
        __syncthreads();
        if (threadIdx.x == 0) {
            out[0] = (float)(-(s_d[0] + s_d[1] + s_d[2] + s_d[3]));
            g_count = 0;   // reset for next graph replay
        }
    }
}

extern "C" void kernel_launch(void* const* d_in, const int* in_sizes, int n_in,
                              void* d_out, int out_size)
{
    const float* i_emb        = (const float*)d_in[0];
    const float* o_emb        = (const float*)d_in[1];
    const int*   target_wids  = (const int*)d_in[2];
    const int*   context_wids = (const int*)d_in[3];
    const int*   neg_wids     = (const int*)d_in[4];
    float*       out          = (float*)d_out;

    const int B = in_sizes[2];
    const int warps_per_block = 128 / 32;   // 4
    int blocks = (B + warps_per_block - 1) / warps_per_block;
    if (blocks > MAX_BLOCKS) blocks = MAX_BLOCKS;   // B=16384 -> 4096 blocks

    cbow_fused_kernel<<<blocks, 128>>>(i_emb, o_emb, target_wids,
                                       context_wids, neg_wids, out, B);
}